// round 1
// baseline (speedup 1.0000x reference)
#include <cuda_runtime.h>
#include <math.h>

#define BB   128               // batch
#define DD   (512*512)         // flattened feature dim = 262144
#define KB   16                // k-tile depth
#define NCTA 296               // 2 CTAs/SM * 148 SMs = one full wave
#define NTILES (DD/KB)         // 16384 k-tiles total

// Scratch (allocation-free rule: __device__ globals)
__device__ float g_dots[BB*BB];   // dots[i][j] = x_i . y_j
__device__ float g_xn2[BB];
__device__ float g_yn2[BB];

__global__ void zero_scratch_kernel() {
    int t = blockIdx.x * blockDim.x + threadIdx.x;
    if (t < BB*BB) g_dots[t] = 0.0f;
    if (t < BB) { g_xn2[t] = 0.0f; g_yn2[t] = 0.0f; }
}

// Split-K fp32 GEMM: each CTA computes the full 128x128 partial product over its
// k-slice, fused with per-row sum-of-squares, then atomically accumulates.
__global__ __launch_bounds__(256, 2)
void gemm_norm_kernel(const float* __restrict__ X, const float* __restrict__ Y) {
    __shared__ float Xs[KB][132];   // k-major, pad 4 floats -> float4-aligned rows
    __shared__ float Ys[KB][132];

    const int t  = threadIdx.x;
    const int tx = t & 15;          // N-tile coord (Y rows)
    const int ty = t >> 4;          // M-tile coord (X rows)
    const int c  = blockIdx.x;

    // Balanced tile distribution: 16384 tiles over 296 CTAs
    const int t0 = (int)(((long long)c       * NTILES) / NCTA);
    const int t1 = (int)(((long long)(c + 1) * NTILES) / NCTA);

    float acc[8][8];
    #pragma unroll
    for (int i = 0; i < 8; i++)
        #pragma unroll
        for (int j = 0; j < 8; j++) acc[i][j] = 0.0f;

    // Load pattern: thread t loads kk = t&15 for rows (t>>4) + 16*i, i=0..7
    // -> 8 fixed rows per thread across the whole k-loop; fuse norm accumulation.
    float snx[8], sny[8];
    #pragma unroll
    for (int i = 0; i < 8; i++) { snx[i] = 0.0f; sny[i] = 0.0f; }

    const int kk_load  = t & 15;
    const int row_base = t >> 4;

    for (int kt = t0; kt < t1; ++kt) {
        const long long kbase = (long long)kt * KB;

        #pragma unroll
        for (int i = 0; i < 8; i++) {
            const int row = row_base + i * 16;
            const float vx = X[(long long)row * DD + kbase + kk_load];
            const float vy = Y[(long long)row * DD + kbase + kk_load];
            Xs[kk_load][row] = vx;
            Ys[kk_load][row] = vy;
            snx[i] += vx * vx;
            sny[i] += vy * vy;
        }
        __syncthreads();

        #pragma unroll
        for (int kk = 0; kk < KB; kk++) {
            float4 a0 = *(const float4*)&Xs[kk][ty * 8];
            float4 a1 = *(const float4*)&Xs[kk][ty * 8 + 4];
            float4 b0 = *(const float4*)&Ys[kk][tx * 8];
            float4 b1 = *(const float4*)&Ys[kk][tx * 8 + 4];
            float a[8] = {a0.x, a0.y, a0.z, a0.w, a1.x, a1.y, a1.z, a1.w};
            float b[8] = {b0.x, b0.y, b0.z, b0.w, b1.x, b1.y, b1.z, b1.w};
            #pragma unroll
            for (int i = 0; i < 8; i++)
                #pragma unroll
                for (int j = 0; j < 8; j++)
                    acc[i][j] = fmaf(a[i], b[j], acc[i][j]);
        }
        __syncthreads();
    }

    // Accumulate partial dots: C[ty*8+i][tx*8+j]
    #pragma unroll
    for (int i = 0; i < 8; i++) {
        const int m = ty * 8 + i;
        #pragma unroll
        for (int j = 0; j < 8; j++) {
            atomicAdd(&g_dots[m * BB + tx * 8 + j], acc[i][j]);
        }
    }

    // Norm reduce: 16 threads (same t>>4, consecutive lanes) share each row set.
    // shfl offsets 1..8 stay within the 16-lane group.
    #pragma unroll
    for (int i = 0; i < 8; i++) {
        float vx = snx[i], vy = sny[i];
        #pragma unroll
        for (int o = 8; o >= 1; o >>= 1) {
            vx += __shfl_xor_sync(0xffffffffu, vx, o);
            vy += __shfl_xor_sync(0xffffffffu, vy, o);
        }
        if ((t & 15) == 0) {
            const int row = row_base + i * 16;
            atomicAdd(&g_xn2[row], vx);
            atomicAdd(&g_yn2[row], vy);
        }
    }
}

// Final rank statistics. sim (post-transpose) row j over i: v_i = dots[i][j]/(xn_i*yn_j).
// JAX semantics: argmax -> first occurrence; top_k -> ties broken by lower index.
__global__ void finalize_kernel(float* __restrict__ out) {
    __shared__ float sxn[BB], syn[BB];
    __shared__ int s_t1, s_t10;

    const int j = threadIdx.x;
    sxn[j] = sqrtf(g_xn2[j]);
    syn[j] = sqrtf(g_yn2[j]);
    if (j == 0) { s_t1 = 0; s_t10 = 0; }
    __syncthreads();

    const float ynj = syn[j];
    const float vdiag = g_dots[j * BB + j] / fmaxf(sxn[j] * ynj, 1e-8f);

    int cnt_gt = 0, cnt_eq_before = 0;
    for (int i = 0; i < BB; i++) {
        if (i == j) continue;
        const float v = g_dots[i * BB + j] / fmaxf(sxn[i] * ynj, 1e-8f);
        if (v > vdiag) cnt_gt++;
        else if (v == vdiag && i < j) cnt_eq_before++;
    }
    const int top1  = (cnt_gt == 0 && cnt_eq_before == 0) ? 1 : 0;
    const int top10 = (cnt_gt + cnt_eq_before < 10) ? 1 : 0;
    atomicAdd(&s_t1, top1);
    atomicAdd(&s_t10, top10);
    __syncthreads();

    if (j == 0) {
        out[0] = (float)s_t1  / (float)BB;
        out[1] = (float)s_t10 / (float)BB;
    }
}

extern "C" void kernel_launch(void* const* d_in, const int* in_sizes, int n_in,
                              void* d_out, int out_size) {
    const float* Z = (const float*)d_in[0];
    const float* Y = (const float*)d_in[1];
    float* out = (float*)d_out;

    zero_scratch_kernel<<<64, 256>>>();          // 16384 threads cover g_dots
    gemm_norm_kernel<<<NCTA, 256>>>(Z, Y);
    finalize_kernel<<<1, BB>>>(out);
}

// round 3
// speedup vs baseline: 2.0099x; 2.0099x over previous
#include <cuda_runtime.h>
#include <cuda_bf16.h>
#include <cstdint>
#include <math.h>

#define BB      128
#define DD      (512*512)          // 262144
#define KT      64                 // k elements per stage
#define NTILES  (DD/KT)            // 4096
#define NCTA    148
#define THREADS 512

// ---- scratch (__device__ globals; allocation-free rule) ----
__device__ float g_part[(size_t)NCTA*BB*BB];   // per-CTA partial dots [c][m][n]
__device__ float g_xn2p[NCTA*BB];
__device__ float g_yn2p[NCTA*BB];
__device__ float g_dots[BB*BB];
__device__ float g_xn2[BB];
__device__ float g_yn2[BB];

__device__ __forceinline__ uint32_t smem_u32(const void* p) {
    uint32_t a;
    asm("{ .reg .u64 t; cvta.to.shared.u64 t, %1; cvt.u32.u64 %0, t; }" : "=r"(a) : "l"(p));
    return a;
}
#define SW128(o) ((uint32_t)(o) ^ ((((uint32_t)(o)) >> 3) & 0x70))

// fp32 pair -> packed bf16x2 hi + bf16x2 lo (memory order [a,b], a in low half)
__device__ __forceinline__ void cvt_hilo(float a, float b, uint32_t& h, uint32_t& l) {
    asm("cvt.rn.bf16x2.f32 %0, %1, %2;" : "=r"(h) : "f"(b), "f"(a));
    float fa = __uint_as_float(h << 16);
    float fb = __uint_as_float(h & 0xffff0000u);
    float la = a - fa, lb = b - fb;
    asm("cvt.rn.bf16x2.f32 %0, %1, %2;" : "=r"(l) : "f"(lb), "f"(la));
}

#define LDSM4(r, addr)                                                          \
    asm volatile("ldmatrix.sync.aligned.m8n8.x4.shared.b16 {%0,%1,%2,%3}, [%4];"\
        : "=r"((r)[0]), "=r"((r)[1]), "=r"((r)[2]), "=r"((r)[3]) : "r"(addr))

#define MMA16816(d, a, b0, b1)                                                  \
    asm volatile("mma.sync.aligned.m16n8k16.row.col.f32.bf16.bf16.f32 "         \
        "{%0,%1,%2,%3}, {%4,%5,%6,%7}, {%8,%9}, {%0,%1,%2,%3};"                 \
        : "+f"((d)[0]), "+f"((d)[1]), "+f"((d)[2]), "+f"((d)[3])                \
        : "r"((a)[0]), "r"((a)[1]), "r"((a)[2]), "r"((a)[3]), "r"(b0), "r"(b1))

// SMEM: 2 stages x 4 tiles (Xh,Xl,Yh,Yl), each 128 rows x 128B (SW128) = 16KB
#define TILE_OFF(p, w) ((p)*65536 + (w)*16384)
#define SMEM_TOTAL (2*65536)

__global__ void __launch_bounds__(THREADS, 1)
gemm_tc_kernel(const float* __restrict__ X, const float* __restrict__ Y) {
    extern __shared__ char smem[];
    const uint32_t sbase = smem_u32(smem);
    const int t    = threadIdx.x;
    const int lane = t & 31;
    const int w    = t >> 5;          // warp 0..15
    const int c    = blockIdx.x;

    // per-warp output slab: rows rb..rb+15, cols cb..cb+63
    const int rb = (w >> 1) * 16;
    const int cb = (w & 1) * 64;

    // ldmatrix lane addressing (tile-relative, before swizzle)
    const int a_row = rb + (lane & 7) + ((lane >> 3) & 1) * 8;
    const int a_kb  = ((lane >> 4) & 1) * 16;
    const int b_row = cb + (lane & 7) + ((lane >> 3) & 1) * 8;
    const int b_kb  = ((lane >> 4) & 1) * 16;

    // loader mapping: thread handles rows grp+32i (i<4), float4 column f4
    const int grp = t >> 4;
    const int f4  = t & 15;

    const int t0 = (int)(((long long)c       * NTILES) / NCTA);
    const int t1 = (int)(((long long)(c + 1) * NTILES) / NCTA);
    const int NT = t1 - t0;

    float acc[8][4];
    #pragma unroll
    for (int j = 0; j < 8; j++)
        #pragma unroll
        for (int q = 0; q < 4; q++) acc[j][q] = 0.0f;

    float snx[4] = {0.f,0.f,0.f,0.f}, sny[4] = {0.f,0.f,0.f,0.f};

    float4 vx[4], vy[4];

    auto load_regs = [&](int kt) {
        const long long kb = (long long)kt * KT + f4 * 4;
        #pragma unroll
        for (int i = 0; i < 4; i++) {
            const int row = grp + 32 * i;
            vx[i] = __ldg((const float4*)(X + (long long)row * DD + kb));
            vy[i] = __ldg((const float4*)(Y + (long long)row * DD + kb));
        }
    };

    auto store_stage = [&](int p) {
        char* xh = smem + TILE_OFF(p, 0);
        char* xl = smem + TILE_OFF(p, 1);
        char* yh = smem + TILE_OFF(p, 2);
        char* yl = smem + TILE_OFF(p, 3);
        #pragma unroll
        for (int i = 0; i < 4; i++) {
            const int row = grp + 32 * i;
            const uint32_t off = SW128(row * 128 + f4 * 8);
            const float4 v = vx[i];
            snx[i] += v.x*v.x + v.y*v.y + v.z*v.z + v.w*v.w;
            uint32_t h0, l0, h1, l1;
            cvt_hilo(v.x, v.y, h0, l0);
            cvt_hilo(v.z, v.w, h1, l1);
            *(uint2*)(xh + off) = make_uint2(h0, h1);
            *(uint2*)(xl + off) = make_uint2(l0, l1);
            const float4 u = vy[i];
            sny[i] += u.x*u.x + u.y*u.y + u.z*u.z + u.w*u.w;
            cvt_hilo(u.x, u.y, h0, l0);
            cvt_hilo(u.z, u.w, h1, l1);
            *(uint2*)(yh + off) = make_uint2(h0, h1);
            *(uint2*)(yl + off) = make_uint2(l0, l1);
        }
    };

    auto compute = [&](int p) {
        const uint32_t xh = sbase + TILE_OFF(p, 0);
        const uint32_t xl = sbase + TILE_OFF(p, 1);
        const uint32_t yh = sbase + TILE_OFF(p, 2);
        const uint32_t yl = sbase + TILE_OFF(p, 3);
        #pragma unroll
        for (int kk = 0; kk < 4; kk++) {
            uint32_t ah[4], al[4];
            const uint32_t aoff = SW128(a_row * 128 + kk * 32 + a_kb);
            LDSM4(ah, xh + aoff);
            LDSM4(al, xl + aoff);
            #pragma unroll
            for (int jp = 0; jp < 4; jp++) {   // pairs of n-tiles
                const uint32_t boff = SW128((b_row + jp * 16) * 128 + kk * 32 + b_kb);
                uint32_t bh[4], bl[4];
                LDSM4(bh, yh + boff);          // bh[0],bh[2] -> j=2jp ; bh[1],bh[3] -> j=2jp+1
                LDSM4(bl, yl + boff);
                const int j0 = jp * 2, j1 = jp * 2 + 1;
                MMA16816(acc[j0], ah, bh[0], bh[2]);
                MMA16816(acc[j1], ah, bh[1], bh[3]);
                MMA16816(acc[j0], ah, bl[0], bl[2]);
                MMA16816(acc[j1], ah, bl[1], bl[3]);
                MMA16816(acc[j0], al, bh[0], bh[2]);
                MMA16816(acc[j1], al, bh[1], bh[3]);
            }
        }
    };

    load_regs(t0);
    store_stage(0);
    __syncthreads();

    for (int s = 0; s < NT; s++) {
        const int p = s & 1;
        if (s + 1 < NT) load_regs(t0 + s + 1);   // LDGs fly while we compute
        compute(p);
        if (s + 1 < NT) store_stage(p ^ 1);
        __syncthreads();
    }

    // norm partials: 16 consecutive lanes share each row set
    #pragma unroll
    for (int i = 0; i < 4; i++) {
        float a = snx[i], b = sny[i];
        #pragma unroll
        for (int o = 8; o >= 1; o >>= 1) {
            a += __shfl_xor_sync(0xffffffffu, a, o);
            b += __shfl_xor_sync(0xffffffffu, b, o);
        }
        if (f4 == 0) {
            const int row = grp + 32 * i;
            g_xn2p[c * BB + row] = a;
            g_yn2p[c * BB + row] = b;
        }
    }

    // epilogue: write per-CTA partial dots from MMA fragments
    // D frag: d0,d1 -> row l/4, cols 2(l%4)+{0,1}; d2,d3 -> row l/4+8
    {
        float* base = &g_part[(size_t)c * (BB * BB)];
        const int r0 = rb + (lane >> 2);
        const int c0 = cb + (lane & 3) * 2;
        #pragma unroll
        for (int j = 0; j < 8; j++) {
            *(float2*)(base + (size_t)r0 * BB + c0 + j * 8)       = make_float2(acc[j][0], acc[j][1]);
            *(float2*)(base + (size_t)(r0 + 8) * BB + c0 + j * 8) = make_float2(acc[j][2], acc[j][3]);
        }
    }
}

// deterministic cross-CTA reduction
__global__ void reduce_kernel() {
    const int b = blockIdx.x, t = threadIdx.x;
    const int idx = b * BB + t;
    float s = 0.f;
    #pragma unroll 4
    for (int c = 0; c < NCTA; c++) s += g_part[(size_t)c * (BB * BB) + idx];
    g_dots[idx] = s;
    if (b == 0) {
        float s2 = 0.f;
        for (int c = 0; c < NCTA; c++) s2 += g_xn2p[c * BB + t];
        g_xn2[t] = s2;
    }
    if (b == 1) {
        float s2 = 0.f;
        for (int c = 0; c < NCTA; c++) s2 += g_yn2p[c * BB + t];
        g_yn2[t] = s2;
    }
}

// rank stats; JAX tie semantics (argmax first occurrence; top_k ties by lower index)
__global__ void finalize_kernel(float* __restrict__ out) {
    __shared__ float sxn[BB], syn[BB];
    __shared__ int s_t1, s_t10;
    const int j = threadIdx.x;
    sxn[j] = sqrtf(g_xn2[j]);
    syn[j] = sqrtf(g_yn2[j]);
    if (j == 0) { s_t1 = 0; s_t10 = 0; }
    __syncthreads();

    const float ynj = syn[j];
    const float vdiag = g_dots[j * BB + j] / fmaxf(sxn[j] * ynj, 1e-8f);
    int cnt_gt = 0, cnt_eq_before = 0;
    #pragma unroll 8
    for (int i = 0; i < BB; i++) {
        if (i == j) continue;
        const float v = g_dots[i * BB + j] / fmaxf(sxn[i] * ynj, 1e-8f);
        if (v > vdiag) cnt_gt++;
        else if (v == vdiag && i < j) cnt_eq_before++;
    }
    atomicAdd(&s_t1,  (cnt_gt == 0 && cnt_eq_before == 0) ? 1 : 0);
    atomicAdd(&s_t10, (cnt_gt + cnt_eq_before < 10) ? 1 : 0);
    __syncthreads();
    if (j == 0) {
        out[0] = (float)s_t1  / (float)BB;
        out[1] = (float)s_t10 / (float)BB;
    }
}

extern "C" void kernel_launch(void* const* d_in, const int* in_sizes, int n_in,
                              void* d_out, int out_size) {
    const float* Z = (const float*)d_in[0];
    const float* Y = (const float*)d_in[1];
    float* out = (float*)d_out;

    cudaFuncSetAttribute(gemm_tc_kernel, cudaFuncAttributeMaxDynamicSharedMemorySize, SMEM_TOTAL);
    gemm_tc_kernel<<<NCTA, THREADS, SMEM_TOTAL>>>(Z, Y);
    reduce_kernel<<<BB, BB>>>();
    finalize_kernel<<<1, BB>>>(out);
}

// round 4
// speedup vs baseline: 2.0730x; 1.0314x over previous
#include <cuda_runtime.h>
#include <cuda_bf16.h>
#include <cstdint>
#include <math.h>

#define BB      128
#define DD      (512*512)          // 262144
#define KT      64                 // k elements per stage
#define NTILES  (DD/KT)            // 4096
#define NCTA    148
#define THREADS 512

// ---- scratch (__device__ globals; allocation-free rule) ----
__device__ float g_part[(size_t)NCTA*BB*BB];   // per-CTA partial dots [c][m][n]
__device__ float g_xn2p[NCTA*BB];
__device__ float g_yn2p[NCTA*BB];
__device__ float g_dots[BB*BB];
__device__ float g_xn2[BB];
__device__ float g_yn2[BB];

__device__ __forceinline__ uint32_t smem_u32(const void* p) {
    uint32_t a;
    asm("{ .reg .u64 t; cvta.to.shared.u64 t, %1; cvt.u32.u64 %0, t; }" : "=r"(a) : "l"(p));
    return a;
}
#define SW128(o) ((uint32_t)(o) ^ ((((uint32_t)(o)) >> 3) & 0x70))

// fp32 pair -> packed bf16x2 hi + bf16x2 lo (memory order [a,b], a in low half)
__device__ __forceinline__ void cvt_hilo(float a, float b, uint32_t& h, uint32_t& l) {
    asm("cvt.rn.bf16x2.f32 %0, %1, %2;" : "=r"(h) : "f"(b), "f"(a));
    float fa = __uint_as_float(h << 16);
    float fb = __uint_as_float(h & 0xffff0000u);
    float la = a - fa, lb = b - fb;
    asm("cvt.rn.bf16x2.f32 %0, %1, %2;" : "=r"(l) : "f"(lb), "f"(la));
}

#define LDSM4(r, addr)                                                          \
    asm volatile("ldmatrix.sync.aligned.m8n8.x4.shared.b16 {%0,%1,%2,%3}, [%4];"\
        : "=r"((r)[0]), "=r"((r)[1]), "=r"((r)[2]), "=r"((r)[3]) : "r"(addr))

#define MMA16816(d, a0, a1, a2, a3, b0, b1)                                     \
    asm volatile("mma.sync.aligned.m16n8k16.row.col.f32.bf16.bf16.f32 "         \
        "{%0,%1,%2,%3}, {%4,%5,%6,%7}, {%8,%9}, {%0,%1,%2,%3};"                 \
        : "+f"((d)[0]), "+f"((d)[1]), "+f"((d)[2]), "+f"((d)[3])                \
        : "r"(a0), "r"(a1), "r"(a2), "r"(a3), "r"(b0), "r"(b1))

// SMEM: 2 stages x 4 tiles (Xh,Xl,Yh,Yl), each 128 rows x 128B (SW128) = 16KB
#define TILE_OFF(p, w) ((p)*65536 + (w)*16384)
#define SMEM_TOTAL (2*65536)

__global__ void __launch_bounds__(THREADS, 1)
gemm_tc_kernel(const float* __restrict__ X, const float* __restrict__ Y) {
    extern __shared__ char smem[];
    const uint32_t sbase = smem_u32(smem);
    const int t    = threadIdx.x;
    const int lane = t & 31;
    const int w    = t >> 5;          // warp 0..15
    const int c    = blockIdx.x;

    // per-warp output slab: rows rb..rb+15, cols cb..cb+63
    const int rb = (w >> 1) * 16;
    const int cb = (w & 1) * 64;

    // ldmatrix lane addressing (tile-relative, before swizzle)
    const int a_row = rb + (lane & 7) + ((lane >> 3) & 1) * 8;
    const int a_kb  = ((lane >> 4) & 1) * 16;
    const int b_row = cb + (lane & 7) + ((lane >> 3) & 1) * 8;
    const int b_kb  = ((lane >> 4) & 1) * 16;

    // loader mapping: thread handles rows grp+32i (i<4), float4 column f4
    const int grp = t >> 4;
    const int f4  = t & 15;

    const int t0 = (int)(((long long)c       * NTILES) / NCTA);
    const int t1 = (int)(((long long)(c + 1) * NTILES) / NCTA);
    const int NT = t1 - t0;

    float acc[8][4];
    #pragma unroll
    for (int j = 0; j < 8; j++)
        #pragma unroll
        for (int q = 0; q < 4; q++) acc[j][q] = 0.0f;

    float snx[4] = {0.f,0.f,0.f,0.f}, sny[4] = {0.f,0.f,0.f,0.f};

    float4 vx[4], vy[4];

    auto load_regs = [&](int kt) {
        const long long kb = (long long)kt * KT + f4 * 4;
        #pragma unroll
        for (int i = 0; i < 4; i++) {
            const int row = grp + 32 * i;
            vx[i] = __ldg((const float4*)(X + (long long)row * DD + kb));
            vy[i] = __ldg((const float4*)(Y + (long long)row * DD + kb));
        }
    };

    auto store_stage = [&](int p) {
        char* xh = smem + TILE_OFF(p, 0);
        char* xl = smem + TILE_OFF(p, 1);
        char* yh = smem + TILE_OFF(p, 2);
        char* yl = smem + TILE_OFF(p, 3);
        #pragma unroll
        for (int i = 0; i < 4; i++) {
            const int row = grp + 32 * i;
            const uint32_t off = SW128(row * 128 + f4 * 8);
            const float4 v = vx[i];
            snx[i] += v.x*v.x + v.y*v.y + v.z*v.z + v.w*v.w;
            uint32_t h0, l0, h1, l1;
            cvt_hilo(v.x, v.y, h0, l0);
            cvt_hilo(v.z, v.w, h1, l1);
            *(uint2*)(xh + off) = make_uint2(h0, h1);
            *(uint2*)(xl + off) = make_uint2(l0, l1);
            const float4 u = vy[i];
            sny[i] += u.x*u.x + u.y*u.y + u.z*u.z + u.w*u.w;
            cvt_hilo(u.x, u.y, h0, l0);
            cvt_hilo(u.z, u.w, h1, l1);
            *(uint2*)(yh + off) = make_uint2(h0, h1);
            *(uint2*)(yl + off) = make_uint2(l0, l1);
        }
    };

    // Term-major MMA schedule: same-accumulator dependency distance = 8 MMAs.
    auto compute = [&](int p) {
        const uint32_t xh = sbase + TILE_OFF(p, 0);
        const uint32_t xl = sbase + TILE_OFF(p, 1);
        const uint32_t yh = sbase + TILE_OFF(p, 2);
        const uint32_t yl = sbase + TILE_OFF(p, 3);
        #pragma unroll
        for (int kk = 0; kk < 4; kk++) {
            uint32_t ah[4], al[4];
            const uint32_t aoff = SW128(a_row * 128 + kk * 32 + a_kb);
            LDSM4(ah, xh + aoff);
            LDSM4(al, xl + aoff);
            uint32_t bh[4][4], bl[4][4];
            #pragma unroll
            for (int jp = 0; jp < 4; jp++) {
                const uint32_t boff = SW128((b_row + jp * 16) * 128 + kk * 32 + b_kb);
                LDSM4(bh[jp], yh + boff);
                LDSM4(bl[jp], yl + boff);
            }
            // hi * hi  (8 independent accumulators)
            #pragma unroll
            for (int jp = 0; jp < 4; jp++) {
                MMA16816(acc[2*jp],   ah[0], ah[1], ah[2], ah[3], bh[jp][0], bh[jp][2]);
                MMA16816(acc[2*jp+1], ah[0], ah[1], ah[2], ah[3], bh[jp][1], bh[jp][3]);
            }
            // hi * lo
            #pragma unroll
            for (int jp = 0; jp < 4; jp++) {
                MMA16816(acc[2*jp],   ah[0], ah[1], ah[2], ah[3], bl[jp][0], bl[jp][2]);
                MMA16816(acc[2*jp+1], ah[0], ah[1], ah[2], ah[3], bl[jp][1], bl[jp][3]);
            }
            // lo * hi
            #pragma unroll
            for (int jp = 0; jp < 4; jp++) {
                MMA16816(acc[2*jp],   al[0], al[1], al[2], al[3], bh[jp][0], bh[jp][2]);
                MMA16816(acc[2*jp+1], al[0], al[1], al[2], al[3], bh[jp][1], bh[jp][3]);
            }
        }
    };

    load_regs(t0);
    store_stage(0);
    __syncthreads();

    for (int s = 0; s < NT; s++) {
        const int p = s & 1;
        if (s + 1 < NT) load_regs(t0 + s + 1);   // LDGs fly while we compute
        compute(p);
        if (s + 1 < NT) store_stage(p ^ 1);
        __syncthreads();
    }

    // norm partials: 16 consecutive lanes share each row set
    #pragma unroll
    for (int i = 0; i < 4; i++) {
        float a = snx[i], b = sny[i];
        #pragma unroll
        for (int o = 8; o >= 1; o >>= 1) {
            a += __shfl_xor_sync(0xffffffffu, a, o);
            b += __shfl_xor_sync(0xffffffffu, b, o);
        }
        if (f4 == 0) {
            const int row = grp + 32 * i;
            g_xn2p[c * BB + row] = a;
            g_yn2p[c * BB + row] = b;
        }
    }

    // epilogue: write per-CTA partial dots from MMA fragments
    {
        float* base = &g_part[(size_t)c * (BB * BB)];
        const int r0 = rb + (lane >> 2);
        const int c0 = cb + (lane & 3) * 2;
        #pragma unroll
        for (int j = 0; j < 8; j++) {
            *(float2*)(base + (size_t)r0 * BB + c0 + j * 8)       = make_float2(acc[j][0], acc[j][1]);
            *(float2*)(base + (size_t)(r0 + 8) * BB + c0 + j * 8) = make_float2(acc[j][2], acc[j][3]);
        }
    }
}

// deterministic cross-CTA reduction (MLP 8)
__global__ void reduce_kernel() {
    const int idx = blockIdx.x * blockDim.x + threadIdx.x;   // 0..16383
    float s = 0.f;
    #pragma unroll 8
    for (int c = 0; c < NCTA; c++) s += g_part[(size_t)c * (BB * BB) + idx];
    g_dots[idx] = s;
    if (idx < BB) {
        float s2 = 0.f;
        #pragma unroll 8
        for (int c = 0; c < NCTA; c++) s2 += g_xn2p[c * BB + idx];
        g_xn2[idx] = s2;
    } else if (idx < 2 * BB) {
        const int r = idx - BB;
        float s2 = 0.f;
        #pragma unroll 8
        for (int c = 0; c < NCTA; c++) s2 += g_yn2p[c * BB + r];
        g_yn2[r] = s2;
    }
}

// rank stats; JAX tie semantics (argmax first occurrence; top_k ties by lower index)
__global__ void finalize_kernel(float* __restrict__ out) {
    __shared__ float sxn[BB], syn[BB];
    __shared__ int s_t1, s_t10;
    const int j = threadIdx.x;
    sxn[j] = sqrtf(g_xn2[j]);
    syn[j] = sqrtf(g_yn2[j]);
    if (j == 0) { s_t1 = 0; s_t10 = 0; }
    __syncthreads();

    const float ynj = syn[j];
    const float vdiag = g_dots[j * BB + j] / fmaxf(sxn[j] * ynj, 1e-8f);
    int cnt_gt = 0, cnt_eq_before = 0;
    #pragma unroll 8
    for (int i = 0; i < BB; i++) {
        if (i == j) continue;
        const float v = g_dots[i * BB + j] / fmaxf(sxn[i] * ynj, 1e-8f);
        if (v > vdiag) cnt_gt++;
        else if (v == vdiag && i < j) cnt_eq_before++;
    }
    atomicAdd(&s_t1,  (cnt_gt == 0 && cnt_eq_before == 0) ? 1 : 0);
    atomicAdd(&s_t10, (cnt_gt + cnt_eq_before < 10) ? 1 : 0);
    __syncthreads();
    if (j == 0) {
        out[0] = (float)s_t1  / (float)BB;
        out[1] = (float)s_t10 / (float)BB;
    }
}

extern "C" void kernel_launch(void* const* d_in, const int* in_sizes, int n_in,
                              void* d_out, int out_size) {
    const float* Z = (const float*)d_in[0];
    const float* Y = (const float*)d_in[1];
    float* out = (float*)d_out;

    cudaFuncSetAttribute(gemm_tc_kernel, cudaFuncAttributeMaxDynamicSharedMemorySize, SMEM_TOTAL);
    gemm_tc_kernel<<<NCTA, THREADS, SMEM_TOTAL>>>(Z, Y);
    reduce_kernel<<<64, 256>>>();
    finalize_kernel<<<1, BB>>>(out);
}

// round 5
// speedup vs baseline: 2.1745x; 1.0490x over previous
#include <cuda_runtime.h>
#include <cuda_bf16.h>
#include <cstdint>
#include <math.h>

#define BB      128
#define DD      (512*512)          // 262144
#define KT      64                 // k elements per stage
#define NTILES  (DD/KT)            // 4096
#define NCTA    148
#define THREADS 512

// ---- scratch (__device__ globals; allocation-free rule) ----
__device__ float g_part[(size_t)NCTA*BB*BB];   // per-CTA partial dots [c][m][n]
__device__ float g_xn2p[NCTA*BB];
__device__ float g_yn2p[NCTA*BB];
__device__ float g_dots[BB*BB];
__device__ float g_xn2[BB];
__device__ float g_yn2[BB];

__device__ __forceinline__ uint32_t smem_u32(const void* p) {
    uint32_t a;
    asm("{ .reg .u64 t; cvta.to.shared.u64 t, %1; cvt.u32.u64 %0, t; }" : "=r"(a) : "l"(p));
    return a;
}
#define SW128(o) ((uint32_t)(o) ^ ((((uint32_t)(o)) >> 3) & 0x70))

// fp32 pair -> packed bf16x2 hi + bf16x2 lo (memory order [a,b], a in low half)
__device__ __forceinline__ void cvt_hilo(float a, float b, uint32_t& h, uint32_t& l) {
    asm("cvt.rn.bf16x2.f32 %0, %1, %2;" : "=r"(h) : "f"(b), "f"(a));
    float fa = __uint_as_float(h << 16);
    float fb = __uint_as_float(h & 0xffff0000u);
    float la = a - fa, lb = b - fb;
    asm("cvt.rn.bf16x2.f32 %0, %1, %2;" : "=r"(l) : "f"(lb), "f"(la));
}

#define LDSM4(r, addr)                                                          \
    asm volatile("ldmatrix.sync.aligned.m8n8.x4.shared.b16 {%0,%1,%2,%3}, [%4];"\
        : "=r"((r)[0]), "=r"((r)[1]), "=r"((r)[2]), "=r"((r)[3]) : "r"(addr))

#define MMA16816(d, a0, a1, a2, a3, b0, b1)                                     \
    asm volatile("mma.sync.aligned.m16n8k16.row.col.f32.bf16.bf16.f32 "         \
        "{%0,%1,%2,%3}, {%4,%5,%6,%7}, {%8,%9}, {%0,%1,%2,%3};"                 \
        : "+f"((d)[0]), "+f"((d)[1]), "+f"((d)[2]), "+f"((d)[3])                \
        : "r"(a0), "r"(a1), "r"(a2), "r"(a3), "r"(b0), "r"(b1))

// SMEM: 2 stages x 4 tiles (Xh,Xl,Yh,Yl), each 128 rows x 128B (SW128) = 16KB
#define TILE_OFF(p, w) ((p)*65536 + (w)*16384)
#define SMEM_TOTAL (2*65536)

__global__ void __launch_bounds__(THREADS, 1)
gemm_tc_kernel(const float* __restrict__ X, const float* __restrict__ Y) {
    extern __shared__ char smem[];
    const uint32_t sbase = smem_u32(smem);
    const int t    = threadIdx.x;
    const int lane = t & 31;
    const int w    = t >> 5;          // warps 0-7: consumers (MMA); 8-15: producers
    const int c    = blockIdx.x;

    const int t0 = (int)(((long long)c       * NTILES) / NCTA);
    const int t1 = (int)(((long long)(c + 1) * NTILES) / NCTA);
    const int NT = t1 - t0;

    if (w < 8) {
        // ---------------- CONSUMER: 32x64 output tile per warp ----------------
        const int rb = (w >> 1) * 32;     // row band
        const int cb = (w & 1) * 64;      // col half

        const int a_row = rb + (lane & 7) + ((lane >> 3) & 1) * 8;
        const int a_kb  = ((lane >> 4) & 1) * 16;
        const int b_row = cb + (lane & 7) + ((lane >> 3) & 1) * 8;
        const int b_kb  = ((lane >> 4) & 1) * 16;

        float acc[16][4];
        #pragma unroll
        for (int j = 0; j < 16; j++)
            #pragma unroll
            for (int q = 0; q < 4; q++) acc[j][q] = 0.0f;

        __syncthreads();   // stage 0 ready

        for (int s = 0; s < NT; s++) {
            const int p = s & 1;
            const uint32_t xh = sbase + TILE_OFF(p, 0);
            const uint32_t xl = sbase + TILE_OFF(p, 1);
            const uint32_t yh = sbase + TILE_OFF(p, 2);
            const uint32_t yl = sbase + TILE_OFF(p, 3);
            #pragma unroll
            for (int kk = 0; kk < 4; kk++) {
                uint32_t ah[8], al[8];
                const uint32_t aoff0 = SW128(a_row * 128 + kk * 32 + a_kb);
                const uint32_t aoff1 = SW128((a_row + 16) * 128 + kk * 32 + a_kb);
                LDSM4(ah + 0, xh + aoff0);
                LDSM4(ah + 4, xh + aoff1);
                LDSM4(al + 0, xl + aoff0);
                LDSM4(al + 4, xl + aoff1);
                #pragma unroll
                for (int nh = 0; nh < 2; nh++) {
                    uint32_t bh[8], bl[8];
                    const uint32_t boff0 = SW128((b_row + nh * 32) * 128 + kk * 32 + b_kb);
                    const uint32_t boff1 = SW128((b_row + nh * 32 + 16) * 128 + kk * 32 + b_kb);
                    LDSM4(bh + 0, yh + boff0);
                    LDSM4(bh + 4, yh + boff1);
                    LDSM4(bl + 0, yl + boff0);
                    LDSM4(bl + 4, yl + boff1);
                    // term-major: 8 independent accumulators per term block
                    #pragma unroll
                    for (int m = 0; m < 2; m++) {
                        MMA16816(acc[m*8+nh*4+0], ah[m*4+0],ah[m*4+1],ah[m*4+2],ah[m*4+3], bh[0], bh[2]);
                        MMA16816(acc[m*8+nh*4+1], ah[m*4+0],ah[m*4+1],ah[m*4+2],ah[m*4+3], bh[1], bh[3]);
                        MMA16816(acc[m*8+nh*4+2], ah[m*4+0],ah[m*4+1],ah[m*4+2],ah[m*4+3], bh[4], bh[6]);
                        MMA16816(acc[m*8+nh*4+3], ah[m*4+0],ah[m*4+1],ah[m*4+2],ah[m*4+3], bh[5], bh[7]);
                    }
                    #pragma unroll
                    for (int m = 0; m < 2; m++) {
                        MMA16816(acc[m*8+nh*4+0], ah[m*4+0],ah[m*4+1],ah[m*4+2],ah[m*4+3], bl[0], bl[2]);
                        MMA16816(acc[m*8+nh*4+1], ah[m*4+0],ah[m*4+1],ah[m*4+2],ah[m*4+3], bl[1], bl[3]);
                        MMA16816(acc[m*8+nh*4+2], ah[m*4+0],ah[m*4+1],ah[m*4+2],ah[m*4+3], bl[4], bl[6]);
                        MMA16816(acc[m*8+nh*4+3], ah[m*4+0],ah[m*4+1],ah[m*4+2],ah[m*4+3], bl[5], bl[7]);
                    }
                    #pragma unroll
                    for (int m = 0; m < 2; m++) {
                        MMA16816(acc[m*8+nh*4+0], al[m*4+0],al[m*4+1],al[m*4+2],al[m*4+3], bh[0], bh[2]);
                        MMA16816(acc[m*8+nh*4+1], al[m*4+0],al[m*4+1],al[m*4+2],al[m*4+3], bh[1], bh[3]);
                        MMA16816(acc[m*8+nh*4+2], al[m*4+0],al[m*4+1],al[m*4+2],al[m*4+3], bh[4], bh[6]);
                        MMA16816(acc[m*8+nh*4+3], al[m*4+0],al[m*4+1],al[m*4+2],al[m*4+3], bh[5], bh[7]);
                    }
                }
            }
            __syncthreads();
        }

        // epilogue: per-CTA partial dots
        float* base = &g_part[(size_t)c * (BB * BB)];
        const int r0 = rb + (lane >> 2);
        const int c0 = cb + (lane & 3) * 2;
        #pragma unroll
        for (int m = 0; m < 2; m++)
            #pragma unroll
            for (int nh = 0; nh < 2; nh++)
                #pragma unroll
                for (int jj = 0; jj < 4; jj++) {
                    const int j = m * 8 + nh * 4 + jj;
                    const int col = c0 + nh * 32 + jj * 8;
                    *(float2*)(base + (size_t)(r0 + m*16)     * BB + col) = make_float2(acc[j][0], acc[j][1]);
                    *(float2*)(base + (size_t)(r0 + m*16 + 8) * BB + col) = make_float2(acc[j][2], acc[j][3]);
                }
    } else {
        // ---------------- PRODUCER: load fp32, split hi/lo, store swizzled ----------------
        const int tp   = (w - 8) * 32 + lane;   // 0..255
        const int prow = tp >> 4;               // rows prow + 16*i, i<8
        const int pf4  = tp & 15;

        float snx[8], sny[8];
        #pragma unroll
        for (int i = 0; i < 8; i++) { snx[i] = 0.f; sny[i] = 0.f; }

        float4 vx[8], vy[8];

        auto load_regs = [&](int kt) {
            const long long kb = (long long)kt * KT + pf4 * 4;
            #pragma unroll
            for (int i = 0; i < 8; i++) {
                const int row = prow + 16 * i;
                vx[i] = __ldg((const float4*)(X + (long long)row * DD + kb));
                vy[i] = __ldg((const float4*)(Y + (long long)row * DD + kb));
            }
        };
        auto store_stage = [&](int p) {
            char* xh = smem + TILE_OFF(p, 0);
            char* xl = smem + TILE_OFF(p, 1);
            char* yh = smem + TILE_OFF(p, 2);
            char* yl = smem + TILE_OFF(p, 3);
            #pragma unroll
            for (int i = 0; i < 8; i++) {
                const int row = prow + 16 * i;
                const uint32_t off = SW128(row * 128 + pf4 * 8);
                const float4 v = vx[i];
                snx[i] += v.x*v.x + v.y*v.y + v.z*v.z + v.w*v.w;
                uint32_t h0, l0, h1, l1;
                cvt_hilo(v.x, v.y, h0, l0);
                cvt_hilo(v.z, v.w, h1, l1);
                *(uint2*)(xh + off) = make_uint2(h0, h1);
                *(uint2*)(xl + off) = make_uint2(l0, l1);
                const float4 u = vy[i];
                sny[i] += u.x*u.x + u.y*u.y + u.z*u.z + u.w*u.w;
                cvt_hilo(u.x, u.y, h0, l0);
                cvt_hilo(u.z, u.w, h1, l1);
                *(uint2*)(yh + off) = make_uint2(h0, h1);
                *(uint2*)(yl + off) = make_uint2(l0, l1);
            }
        };

        load_regs(t0);
        store_stage(0);
        __syncthreads();

        for (int s = 0; s < NT; s++) {
            if (s + 1 < NT) {
                load_regs(t0 + s + 1);
                store_stage((s + 1) & 1);
            }
            __syncthreads();
        }

        // norm partials: 16 consecutive lanes share each row set
        #pragma unroll
        for (int i = 0; i < 8; i++) {
            float a = snx[i], b = sny[i];
            #pragma unroll
            for (int o = 8; o >= 1; o >>= 1) {
                a += __shfl_xor_sync(0xffffffffu, a, o);
                b += __shfl_xor_sync(0xffffffffu, b, o);
            }
            if (pf4 == 0) {
                const int row = prow + 16 * i;
                g_xn2p[c * BB + row] = a;
                g_yn2p[c * BB + row] = b;
            }
        }
    }
}

// deterministic cross-CTA reduction (coalesced; MLP 8)
__global__ void reduce_kernel() {
    const int idx = blockIdx.x * blockDim.x + threadIdx.x;   // 0..16383
    float s = 0.f;
    #pragma unroll 8
    for (int c = 0; c < NCTA; c++) s += g_part[(size_t)c * (BB * BB) + idx];
    g_dots[idx] = s;
    if (idx < BB) {
        float s2 = 0.f;
        #pragma unroll 8
        for (int c = 0; c < NCTA; c++) s2 += g_xn2p[c * BB + idx];
        g_xn2[idx] = s2;
    } else if (idx < 2 * BB) {
        const int r = idx - BB;
        float s2 = 0.f;
        #pragma unroll 8
        for (int c = 0; c < NCTA; c++) s2 += g_yn2p[c * BB + r];
        g_yn2[r] = s2;
    }
}

// rank stats; JAX tie semantics (argmax first occurrence; top_k ties by lower index)
__global__ void finalize_kernel(float* __restrict__ out) {
    __shared__ float sxn[BB], syn[BB];
    __shared__ int s_t1, s_t10;
    const int j = threadIdx.x;
    sxn[j] = sqrtf(g_xn2[j]);
    syn[j] = sqrtf(g_yn2[j]);
    if (j == 0) { s_t1 = 0; s_t10 = 0; }
    __syncthreads();

    const float ynj = syn[j];
    const float vdiag = g_dots[j * BB + j] / fmaxf(sxn[j] * ynj, 1e-8f);
    int cnt_gt = 0, cnt_eq_before = 0;
    #pragma unroll 8
    for (int i = 0; i < BB; i++) {
        if (i == j) continue;
        const float v = g_dots[i * BB + j] / fmaxf(sxn[i] * ynj, 1e-8f);
        if (v > vdiag) cnt_gt++;
        else if (v == vdiag && i < j) cnt_eq_before++;
    }
    atomicAdd(&s_t1,  (cnt_gt == 0 && cnt_eq_before == 0) ? 1 : 0);
    atomicAdd(&s_t10, (cnt_gt + cnt_eq_before < 10) ? 1 : 0);
    __syncthreads();
    if (j == 0) {
        out[0] = (float)s_t1  / (float)BB;
        out[1] = (float)s_t10 / (float)BB;
    }
}

extern "C" void kernel_launch(void* const* d_in, const int* in_sizes, int n_in,
                              void* d_out, int out_size) {
    const float* Z = (const float*)d_in[0];
    const float* Y = (const float*)d_in[1];
    float* out = (float*)d_out;

    cudaFuncSetAttribute(gemm_tc_kernel, cudaFuncAttributeMaxDynamicSharedMemorySize, SMEM_TOTAL);
    gemm_tc_kernel<<<NCTA, THREADS, SMEM_TOTAL>>>(Z, Y);
    reduce_kernel<<<128, 128>>>();
    finalize_kernel<<<1, BB>>>(out);
}

// round 6
// speedup vs baseline: 2.6623x; 1.2243x over previous
#include <cuda_runtime.h>
#include <cuda_bf16.h>
#include <cstdint>
#include <math.h>

#define BB      128
#define DD      (512*512)          // 262144
#define KT      64                 // k elements per stage
#define NTILES  (DD/KT)            // 4096
#define NCTA    148
#define THREADS 512

// ---- scratch (__device__ globals; allocation-free rule) ----
__device__ float g_part[(size_t)NCTA*BB*BB];   // per-CTA partial dots [c][m][n]
__device__ float g_xn2p[NCTA*BB];
__device__ float g_yn2p[NCTA*BB];
__device__ float g_dots[BB*BB];
__device__ float g_xn2[BB];
__device__ float g_yn2[BB];
__device__ int   g_it1, g_it10, g_tick;

__device__ __forceinline__ uint32_t smem_u32(const void* p) {
    uint32_t a;
    asm("{ .reg .u64 t; cvta.to.shared.u64 t, %1; cvt.u32.u64 %0, t; }" : "=r"(a) : "l"(p));
    return a;
}
#define SW128(o) ((uint32_t)(o) ^ ((((uint32_t)(o)) >> 3) & 0x70))

// fp32 pair -> packed bf16x2 hi + bf16x2 lo (memory order [a,b], a in low half)
__device__ __forceinline__ void cvt_hilo(float a, float b, uint32_t& h, uint32_t& l) {
    asm("cvt.rn.bf16x2.f32 %0, %1, %2;" : "=r"(h) : "f"(b), "f"(a));
    float fa = __uint_as_float(h << 16);
    float fb = __uint_as_float(h & 0xffff0000u);
    float la = a - fa, lb = b - fb;
    asm("cvt.rn.bf16x2.f32 %0, %1, %2;" : "=r"(l) : "f"(lb), "f"(la));
}

#define LDSM4(r, addr)                                                          \
    asm volatile("ldmatrix.sync.aligned.m8n8.x4.shared.b16 {%0,%1,%2,%3}, [%4];"\
        : "=r"((r)[0]), "=r"((r)[1]), "=r"((r)[2]), "=r"((r)[3]) : "r"(addr))

#define MMA16816(d, a0, a1, a2, a3, b0, b1)                                     \
    asm volatile("mma.sync.aligned.m16n8k16.row.col.f32.bf16.bf16.f32 "         \
        "{%0,%1,%2,%3}, {%4,%5,%6,%7}, {%8,%9}, {%0,%1,%2,%3};"                 \
        : "+f"((d)[0]), "+f"((d)[1]), "+f"((d)[2]), "+f"((d)[3])                \
        : "r"(a0), "r"(a1), "r"(a2), "r"(a3), "r"(b0), "r"(b1))

// SMEM: 2 stages x 4 tiles (Xh,Xl,Yh,Yl), each 128 rows x 128B (SW128) = 16KB
#define TILE_OFF(p, w) ((p)*65536 + (w)*16384)
#define SMEM_TOTAL (2*65536)

__global__ void __launch_bounds__(THREADS, 1)
gemm_tc_kernel(const float* __restrict__ X, const float* __restrict__ Y) {
    extern __shared__ char smem[];
    const uint32_t sbase = smem_u32(smem);
    const int t    = threadIdx.x;
    const int lane = t & 31;
    const int w    = t >> 5;          // warps 0-7: consumers (MMA); 8-15: producers
    const int c    = blockIdx.x;

    const int t0 = (int)(((long long)c       * NTILES) / NCTA);
    const int t1 = (int)(((long long)(c + 1) * NTILES) / NCTA);
    const int NT = t1 - t0;

    if (w < 8) {
        // ---------------- CONSUMER: 32x64 output tile per warp ----------------
        const int rb = (w >> 1) * 32;     // row band
        const int cb = (w & 1) * 64;      // col half

        const int a_row = rb + (lane & 7) + ((lane >> 3) & 1) * 8;
        const int a_kb  = ((lane >> 4) & 1) * 16;
        const int b_row = cb + (lane & 7) + ((lane >> 3) & 1) * 8;
        const int b_kb  = ((lane >> 4) & 1) * 16;

        float acc[16][4];
        #pragma unroll
        for (int j = 0; j < 16; j++)
            #pragma unroll
            for (int q = 0; q < 4; q++) acc[j][q] = 0.0f;

        __syncthreads();   // stage 0 ready

        for (int s = 0; s < NT; s++) {
            const int p = s & 1;
            const uint32_t xh = sbase + TILE_OFF(p, 0);
            const uint32_t xl = sbase + TILE_OFF(p, 1);
            const uint32_t yh = sbase + TILE_OFF(p, 2);
            const uint32_t yl = sbase + TILE_OFF(p, 3);
            #pragma unroll
            for (int kk = 0; kk < 4; kk++) {
                uint32_t ah[8], al[8];
                const uint32_t aoff0 = SW128(a_row * 128 + kk * 32 + a_kb);
                const uint32_t aoff1 = SW128((a_row + 16) * 128 + kk * 32 + a_kb);
                LDSM4(ah + 0, xh + aoff0);
                LDSM4(ah + 4, xh + aoff1);
                LDSM4(al + 0, xl + aoff0);
                LDSM4(al + 4, xl + aoff1);
                #pragma unroll
                for (int nh = 0; nh < 2; nh++) {
                    uint32_t bh[8], bl[8];
                    const uint32_t boff0 = SW128((b_row + nh * 32) * 128 + kk * 32 + b_kb);
                    const uint32_t boff1 = SW128((b_row + nh * 32 + 16) * 128 + kk * 32 + b_kb);
                    LDSM4(bh + 0, yh + boff0);
                    LDSM4(bh + 4, yh + boff1);
                    LDSM4(bl + 0, yl + boff0);
                    LDSM4(bl + 4, yl + boff1);
                    // term order: hh, lh, hl  (bl gets ~16 MMAs of latency cover)
                    #pragma unroll
                    for (int m = 0; m < 2; m++) {
                        MMA16816(acc[m*8+nh*4+0], ah[m*4+0],ah[m*4+1],ah[m*4+2],ah[m*4+3], bh[0], bh[2]);
                        MMA16816(acc[m*8+nh*4+1], ah[m*4+0],ah[m*4+1],ah[m*4+2],ah[m*4+3], bh[1], bh[3]);
                        MMA16816(acc[m*8+nh*4+2], ah[m*4+0],ah[m*4+1],ah[m*4+2],ah[m*4+3], bh[4], bh[6]);
                        MMA16816(acc[m*8+nh*4+3], ah[m*4+0],ah[m*4+1],ah[m*4+2],ah[m*4+3], bh[5], bh[7]);
                    }
                    #pragma unroll
                    for (int m = 0; m < 2; m++) {
                        MMA16816(acc[m*8+nh*4+0], al[m*4+0],al[m*4+1],al[m*4+2],al[m*4+3], bh[0], bh[2]);
                        MMA16816(acc[m*8+nh*4+1], al[m*4+0],al[m*4+1],al[m*4+2],al[m*4+3], bh[1], bh[3]);
                        MMA16816(acc[m*8+nh*4+2], al[m*4+0],al[m*4+1],al[m*4+2],al[m*4+3], bh[4], bh[6]);
                        MMA16816(acc[m*8+nh*4+3], al[m*4+0],al[m*4+1],al[m*4+2],al[m*4+3], bh[5], bh[7]);
                    }
                    #pragma unroll
                    for (int m = 0; m < 2; m++) {
                        MMA16816(acc[m*8+nh*4+0], ah[m*4+0],ah[m*4+1],ah[m*4+2],ah[m*4+3], bl[0], bl[2]);
                        MMA16816(acc[m*8+nh*4+1], ah[m*4+0],ah[m*4+1],ah[m*4+2],ah[m*4+3], bl[1], bl[3]);
                        MMA16816(acc[m*8+nh*4+2], ah[m*4+0],ah[m*4+1],ah[m*4+2],ah[m*4+3], bl[4], bl[6]);
                        MMA16816(acc[m*8+nh*4+3], ah[m*4+0],ah[m*4+1],ah[m*4+2],ah[m*4+3], bl[5], bl[7]);
                    }
                }
            }
            __syncthreads();
        }

        // epilogue: per-CTA partial dots
        float* base = &g_part[(size_t)c * (BB * BB)];
        const int r0 = rb + (lane >> 2);
        const int c0 = cb + (lane & 3) * 2;
        #pragma unroll
        for (int m = 0; m < 2; m++)
            #pragma unroll
            for (int nh = 0; nh < 2; nh++)
                #pragma unroll
                for (int jj = 0; jj < 4; jj++) {
                    const int j = m * 8 + nh * 4 + jj;
                    const int col = c0 + nh * 32 + jj * 8;
                    *(float2*)(base + (size_t)(r0 + m*16)     * BB + col) = make_float2(acc[j][0], acc[j][1]);
                    *(float2*)(base + (size_t)(r0 + m*16 + 8) * BB + col) = make_float2(acc[j][2], acc[j][3]);
                }
    } else {
        // ---------------- PRODUCER: load fp32, split hi/lo, store swizzled ----------------
        const int tp   = (w - 8) * 32 + lane;   // 0..255
        const int prow = tp >> 4;               // rows prow + 16*i, i<8
        const int pf4  = tp & 15;

        float snx[8], sny[8];
        #pragma unroll
        for (int i = 0; i < 8; i++) { snx[i] = 0.f; sny[i] = 0.f; }

        float4 vx[8], vy[8];

        auto load_regs = [&](int kt) {
            const long long kb = (long long)kt * KT + pf4 * 4;
            #pragma unroll
            for (int i = 0; i < 8; i++) {
                const int row = prow + 16 * i;
                vx[i] = __ldg((const float4*)(X + (long long)row * DD + kb));
                vy[i] = __ldg((const float4*)(Y + (long long)row * DD + kb));
            }
        };
        auto store_stage = [&](int p) {
            char* xh = smem + TILE_OFF(p, 0);
            char* xl = smem + TILE_OFF(p, 1);
            char* yh = smem + TILE_OFF(p, 2);
            char* yl = smem + TILE_OFF(p, 3);
            #pragma unroll
            for (int i = 0; i < 8; i++) {
                const int row = prow + 16 * i;
                const uint32_t off = SW128(row * 128 + pf4 * 8);
                const float4 v = vx[i];
                snx[i] += v.x*v.x + v.y*v.y + v.z*v.z + v.w*v.w;
                uint32_t h0, l0, h1, l1;
                cvt_hilo(v.x, v.y, h0, l0);
                cvt_hilo(v.z, v.w, h1, l1);
                *(uint2*)(xh + off) = make_uint2(h0, h1);
                *(uint2*)(xl + off) = make_uint2(l0, l1);
                const float4 u = vy[i];
                sny[i] += u.x*u.x + u.y*u.y + u.z*u.z + u.w*u.w;
                cvt_hilo(u.x, u.y, h0, l0);
                cvt_hilo(u.z, u.w, h1, l1);
                *(uint2*)(yh + off) = make_uint2(h0, h1);
                *(uint2*)(yl + off) = make_uint2(l0, l1);
            }
        };

        load_regs(t0);
        store_stage(0);
        __syncthreads();

        for (int s = 0; s < NT; s++) {
            if (s + 1 < NT) {
                load_regs(t0 + s + 1);
                store_stage((s + 1) & 1);
            }
            __syncthreads();
        }

        // norm partials: 16 consecutive lanes share each row set
        #pragma unroll
        for (int i = 0; i < 8; i++) {
            float a = snx[i], b = sny[i];
            #pragma unroll
            for (int o = 8; o >= 1; o >>= 1) {
                a += __shfl_xor_sync(0xffffffffu, a, o);
                b += __shfl_xor_sync(0xffffffffu, b, o);
            }
            if (pf4 == 0) {
                const int row = prow + 16 * i;
                g_xn2p[c * BB + row] = a;
                g_yn2p[c * BB + row] = b;
            }
        }
    }
}

// deterministic cross-CTA reduction, float4-wide; also zeroes finalize counters
__global__ void reduce_kernel() {
    const int i4 = blockIdx.x * blockDim.x + threadIdx.x;   // 0..4095
    if (i4 == 0) { g_it1 = 0; g_it10 = 0; g_tick = 0; }
    float4 s = make_float4(0.f, 0.f, 0.f, 0.f);
    #pragma unroll 4
    for (int c = 0; c < NCTA; c++) {
        const float4 v = *(const float4*)&g_part[(size_t)c * (BB * BB) + i4 * 4];
        s.x += v.x; s.y += v.y; s.z += v.z; s.w += v.w;
    }
    *(float4*)&g_dots[i4 * 4] = s;
    if (i4 < BB) {
        float s2 = 0.f;
        #pragma unroll 8
        for (int c = 0; c < NCTA; c++) s2 += g_xn2p[c * BB + i4];
        g_xn2[i4] = s2;
    } else if (i4 < 2 * BB) {
        const int r = i4 - BB;
        float s2 = 0.f;
        #pragma unroll 8
        for (int c = 0; c < NCTA; c++) s2 += g_yn2p[c * BB + r];
        g_yn2[r] = s2;
    }
}

// parallel finalize: CTA j handles sim column j (post-transpose row j).
// v_i = dots[i][j] / max(xn_i * yn_j, eps). JAX ties: lower index wins.
// Deterministic: integer atomics only; last CTA (ticket) writes output.
__global__ void finalize_kernel(float* __restrict__ out) {
    __shared__ float s_vd;
    __shared__ int s_gt, s_eqb;
    const int j = blockIdx.x;
    const int i = threadIdx.x;

    const float ynj = sqrtf(g_yn2[j]);
    const float xni = sqrtf(g_xn2[i]);
    const float v = g_dots[i * BB + j] / fmaxf(xni * ynj, 1e-8f);

    if (i == 0) { s_gt = 0; s_eqb = 0; }
    if (i == j) s_vd = v;
    __syncthreads();
    const float vd = s_vd;

    const bool gt  = (i != j) && (v > vd);
    const bool eqb = (i != j) && (v == vd) && (i < j);
    const unsigned mgt  = __ballot_sync(0xffffffffu, gt);
    const unsigned meqb = __ballot_sync(0xffffffffu, eqb);
    if ((i & 31) == 0) {
        if (mgt)  atomicAdd(&s_gt,  __popc(mgt));
        if (meqb) atomicAdd(&s_eqb, __popc(meqb));
    }
    __syncthreads();

    if (i == 0) {
        const int rank = s_gt + s_eqb;
        atomicAdd(&g_it1,  (rank == 0) ? 1 : 0);
        atomicAdd(&g_it10, (rank < 10) ? 1 : 0);
        __threadfence();
        const int tick = atomicAdd(&g_tick, 1);
        if (tick == BB - 1) {
            __threadfence();
            out[0] = (float)g_it1  / (float)BB;
            out[1] = (float)g_it10 / (float)BB;
        }
    }
}

extern "C" void kernel_launch(void* const* d_in, const int* in_sizes, int n_in,
                              void* d_out, int out_size) {
    const float* Z = (const float*)d_in[0];
    const float* Y = (const float*)d_in[1];
    float* out = (float*)d_out;

    cudaFuncSetAttribute(gemm_tc_kernel, cudaFuncAttributeMaxDynamicSharedMemorySize, SMEM_TOTAL);
    gemm_tc_kernel<<<NCTA, THREADS, SMEM_TOTAL>>>(Z, Y);
    reduce_kernel<<<32, 128>>>();
    finalize_kernel<<<BB, BB>>>(out);
}